// round 13
// baseline (speedup 1.0000x reference)
#include <cuda_runtime.h>
#include <cuda_bf16.h>
#include <cstddef>

// Enframe: x (8,2,480000) f32 -> out (8,4096,934) f32
//   out[bc, q*512 + r, t] = x[bc, (t+q)*512 + r],  bc = b*2+c, q in [0,4)
// R12 structure (tile 128t x 32r, 2048 blocks, MLP=5 load batch, __stcs
// STG.64, per-row t-shift delta = 2*(row mod 4) for 32B-aligned runs).
// R13 change: smem padded to 32KB -> 7 blocks/SM (148*7 = 1036 concurrent)
// so 2048 blocks = 1.98 waves (vs 1.73 at occ 8): wave-tail idle 13.5% -> 1.2%.

#define S_LEN     480000
#define T_OUT     934          // (480000 - 2048)/512 + 1
#define SLOTS     937          // max slot = 933 + 3 = 936
#define ROWS      2048         // per-bc output rows
#define R_PAD     33
#define T_TILE    128
#define SLOT_NEED 137          // max slot row touched = 136 (t 133 + q 3 -> +pair)
#define SMEM_FLOATS 8192       // 32 KB static smem -> exactly 7 blocks/SM

__global__ __launch_bounds__(256) void enframe_kernel(const float4* __restrict__ x4,
                                                      float* __restrict__ out) {
    __shared__ float tile[SMEM_FLOATS];   // used: 137*33 = 4521 floats; padded for occ=7

    const int rt = blockIdx.x;   // 0..15  r base = rt*32
    const int tt = blockIdx.y;   // 0..7   t base = tt*128
    const int bc = blockIdx.z;   // 0..15
    const int tx = threadIdx.x;  // 0..31
    const int ty = threadIdx.y;  // 0..7

    const int tb = tt * T_TILE;
    const float4* __restrict__ xin = x4 + (size_t)bc * (S_LEN / 4);
    // interior tiles tt<7: max t = tb+133 <= 901 < 934, max s = tb+136 <= 904 < 937
    const bool interior = (tt < 7);

    // ---- Load phase: batch all 5 LDG.128 (MLP=5), then conflict-free STS ----
    const int c    = tx & 7;               // float4 column: r = rt*32 + 4c + j
    const int lrow = ty * 4 + (tx >> 3);   // 0..31

    float4 v[5];
#pragma unroll
    for (int p = 0; p < 5; ++p) {
        const int row = p * 32 + lrow;
        v[p] = make_float4(0.f, 0.f, 0.f, 0.f);
        if (row < SLOT_NEED) {
            const int s = tb + row;
            if (interior || s < SLOTS) v[p] = xin[(size_t)s * 128 + rt * 8 + c];
        }
    }
#pragma unroll
    for (int p = 0; p < 5; ++p) {
        const int row = p * 32 + lrow;
        if (row < SLOT_NEED) {
            float* dst = &tile[row * R_PAD + 4 * c];   // banks all distinct
            dst[0] = v[p].x; dst[1] = v[p].y; dst[2] = v[p].z; dst[3] = v[p].w;
        }
    }
    __syncthreads();

    // ---- Store phase: warp ty -> (q = ty>>1, half = ty&1); lane = t pair ----
    // Row rl has shift delta = 2*(rl mod 4); loop j = rl mod 4, m = rl / 4.
    const int q    = ty >> 1;
    const int half = ty & 1;
    const int t0   = tb + half * 64 + 2 * tx;   // even
    const int row0 = half * 64 + 2 * tx + q;    // slot row for t0

    float* __restrict__ outq = out + (size_t)bc * ROWS * T_OUT
                                   + (size_t)(q * 512 + rt * 32) * T_OUT;

#pragma unroll
    for (int j = 0; j < 4; ++j) {               // delta = 2j
        const int t = t0 + 2 * j;
        const float* __restrict__ src = &tile[(row0 + 2 * j) * R_PAD];
        if (interior || t < T_OUT) {            // t even, T_OUT even -> pair valid
            float* o = outq + (size_t)j * T_OUT + t;
#pragma unroll
            for (int m = 0; m < 8; ++m) {
                const int rl = 4 * m + j;       // rows with rl mod 4 == j
                float2 w;
                w.x = src[rl];                  // tile[row][rl]
                w.y = src[R_PAD + rl];          // tile[row+1][rl] -> t+1
                __stcs((float2*)(o + (size_t)(4 * m) * T_OUT), w);  // 32B-aligned run
            }
        }
    }

    // ---- tt==0: prepend uncovered heads t in [0, 2j) for rows rl == j (mod 4) ----
    if (tt == 0 && half == 0 && tx >= 29) {
        const int p = 31 - tx;                  // pair index 0..2
#pragma unroll
        for (int j = 1; j < 4; ++j) {
            if (p < j) {
                const int t = 2 * p;
                const float* __restrict__ src = &tile[(2 * p + q) * R_PAD];
                float* o = outq + (size_t)j * T_OUT + t;
#pragma unroll
                for (int m = 0; m < 8; ++m) {
                    const int rl = 4 * m + j;
                    float2 w;
                    w.x = src[rl];
                    w.y = src[R_PAD + rl];
                    __stcs((float2*)(o + (size_t)(4 * m) * T_OUT), w);
                }
            }
        }
    }
}

extern "C" void kernel_launch(void* const* d_in, const int* in_sizes, int n_in,
                              void* d_out, int out_size) {
    const float4* x = (const float4*)d_in[0];
    float* out = (float*)d_out;

    dim3 block(32, 8, 1);
    dim3 grid(16, 8, 16);   // (r tiles of 32, t tiles of 128, bc)
    enframe_kernel<<<grid, block>>>(x, out);
}

// round 14
// speedup vs baseline: 1.2193x; 1.2193x over previous
#include <cuda_runtime.h>
#include <cuda_bf16.h>
#include <cstddef>

// Enframe: x (8,2,480000) f32 -> out (8,4096,934) f32
//   out[bc, q*512 + r, t] = x[bc, (t+q)*512 + r],  bc = b*2+c, q in [0,4)
// R12 structure (best: tile 128t x 32r, 2048 blocks, MLP=5 load batch,
// __stcs STG.64, per-row t-shift delta = 2*(row mod 4) -> 32B-aligned runs).
// R14 change: input LDG.128 via __ldcs (evict-first) — input is single-use,
// keep L2 for the output write stream.

#define S_LEN     480000
#define T_OUT     934          // (480000 - 2048)/512 + 1
#define SLOTS     937          // max slot = 933 + 3 = 936
#define ROWS      2048         // per-bc output rows
#define R_PAD     33
#define T_TILE    128
#define SLOT_NEED 137          // max slot row touched = 136

__global__ __launch_bounds__(256) void enframe_kernel(const float4* __restrict__ x4,
                                                      float* __restrict__ out) {
    __shared__ float tile[SLOT_NEED * R_PAD];   // 137*33*4 = 18084 B -> 8 blocks/SM

    const int rt = blockIdx.x;   // 0..15  r base = rt*32
    const int tt = blockIdx.y;   // 0..7   t base = tt*128
    const int bc = blockIdx.z;   // 0..15
    const int tx = threadIdx.x;  // 0..31
    const int ty = threadIdx.y;  // 0..7

    const int tb = tt * T_TILE;
    const float4* __restrict__ xin = x4 + (size_t)bc * (S_LEN / 4);
    // interior tiles tt<7: max t = tb+133 <= 901 < 934, max s = tb+136 <= 904 < 937
    const bool interior = (tt < 7);

    // ---- Load phase: batch all 5 LDG.128 (MLP=5, evict-first), then STS ----
    const int c    = tx & 7;               // float4 column: r = rt*32 + 4c + j
    const int lrow = ty * 4 + (tx >> 3);   // 0..31

    float4 v[5];
#pragma unroll
    for (int p = 0; p < 5; ++p) {
        const int row = p * 32 + lrow;
        v[p] = make_float4(0.f, 0.f, 0.f, 0.f);
        if (row < SLOT_NEED) {
            const int s = tb + row;
            if (interior || s < SLOTS) v[p] = __ldcs(&xin[(size_t)s * 128 + rt * 8 + c]);
        }
    }
#pragma unroll
    for (int p = 0; p < 5; ++p) {
        const int row = p * 32 + lrow;
        if (row < SLOT_NEED) {
            float* dst = &tile[row * R_PAD + 4 * c];   // banks all distinct
            dst[0] = v[p].x; dst[1] = v[p].y; dst[2] = v[p].z; dst[3] = v[p].w;
        }
    }
    __syncthreads();

    // ---- Store phase: warp ty -> (q = ty>>1, half = ty&1); lane = t pair ----
    // Row rl has shift delta = 2*(rl mod 4); loop j = rl mod 4, m = rl / 4.
    const int q    = ty >> 1;
    const int half = ty & 1;
    const int t0   = tb + half * 64 + 2 * tx;   // even
    const int row0 = half * 64 + 2 * tx + q;    // slot row for t0

    float* __restrict__ outq = out + (size_t)bc * ROWS * T_OUT
                                   + (size_t)(q * 512 + rt * 32) * T_OUT;

#pragma unroll
    for (int j = 0; j < 4; ++j) {               // delta = 2j
        const int t = t0 + 2 * j;
        const float* __restrict__ src = &tile[(row0 + 2 * j) * R_PAD];
        if (interior || t < T_OUT) {            // t even, T_OUT even -> pair valid
            float* o = outq + (size_t)j * T_OUT + t;
#pragma unroll
            for (int m = 0; m < 8; ++m) {
                const int rl = 4 * m + j;       // rows with rl mod 4 == j
                float2 w;
                w.x = src[rl];                  // tile[row][rl]
                w.y = src[R_PAD + rl];          // tile[row+1][rl] -> t+1
                __stcs((float2*)(o + (size_t)(4 * m) * T_OUT), w);  // 32B-aligned run
            }
        }
    }

    // ---- tt==0: prepend uncovered heads t in [0, 2j) for rows rl == j (mod 4) ----
    if (tt == 0 && half == 0 && tx >= 29) {
        const int p = 31 - tx;                  // pair index 0..2
#pragma unroll
        for (int j = 1; j < 4; ++j) {
            if (p < j) {
                const int t = 2 * p;
                const float* __restrict__ src = &tile[(2 * p + q) * R_PAD];
                float* o = outq + (size_t)j * T_OUT + t;
#pragma unroll
                for (int m = 0; m < 8; ++m) {
                    const int rl = 4 * m + j;
                    float2 w;
                    w.x = src[rl];
                    w.y = src[R_PAD + rl];
                    __stcs((float2*)(o + (size_t)(4 * m) * T_OUT), w);
                }
            }
        }
    }
}

extern "C" void kernel_launch(void* const* d_in, const int* in_sizes, int n_in,
                              void* d_out, int out_size) {
    const float4* x = (const float4*)d_in[0];
    float* out = (float*)d_out;

    dim3 block(32, 8, 1);
    dim3 grid(16, 8, 16);   // (r tiles of 32, t tiles of 128, bc)
    enframe_kernel<<<grid, block>>>(x, out);
}

// round 15
// speedup vs baseline: 1.3333x; 1.0935x over previous
#include <cuda_runtime.h>
#include <cuda_bf16.h>
#include <cstddef>

// Enframe: x (8,2,480000) f32 -> out (8,4096,934) f32
//   out[bc, q*512 + r, t] = x[bc, (t+q)*512 + r],  bc = b*2+c, q in [0,4)
// FINAL (= R12, best measured: 24.2us kernel / 26.7us harness, 3.94 TB/s):
//  - tile 128t x 32r in smem (transpose through conflict-free padded tile)
//  - 2048 blocks, 8 blocks/SM
//  - load phase: all 5 LDG.128 batched first (MLP=5), default cache policy
//    (input has cross-tile reuse; __ldcs measured as a regression)
//  - store phase: STG.64 __stcs (write-once output), 256B runs per row,
//    per-row t-shift delta = 2*(row mod 4) so every run starts 32B-sector-
//    aligned (byte addr = 24*row + 4*t mod 32 == 0 <=> t == 2*row mod 8)

#define S_LEN     480000
#define T_OUT     934          // (480000 - 2048)/512 + 1
#define SLOTS     937          // max slot = 933 + 3 = 936
#define ROWS      2048         // per-bc output rows
#define R_PAD     33
#define T_TILE    128
#define SLOT_NEED 137          // max slot row touched = 136 (t 133 + q 3 + pair)

__global__ __launch_bounds__(256) void enframe_kernel(const float4* __restrict__ x4,
                                                      float* __restrict__ out) {
    __shared__ float tile[SLOT_NEED * R_PAD];   // 137*33*4 = 18084 B

    const int rt = blockIdx.x;   // 0..15  r base = rt*32
    const int tt = blockIdx.y;   // 0..7   t base = tt*128
    const int bc = blockIdx.z;   // 0..15
    const int tx = threadIdx.x;  // 0..31
    const int ty = threadIdx.y;  // 0..7

    const int tb = tt * T_TILE;
    const float4* __restrict__ xin = x4 + (size_t)bc * (S_LEN / 4);
    // interior tiles tt<7: max t = tb+133 <= 901 < 934, max s = tb+136 <= 904 < 937
    const bool interior = (tt < 7);

    // ---- Load phase: batch all 5 LDG.128 (MLP=5), then conflict-free STS ----
    const int c    = tx & 7;               // float4 column: r = rt*32 + 4c + j
    const int lrow = ty * 4 + (tx >> 3);   // 0..31

    float4 v[5];
#pragma unroll
    for (int p = 0; p < 5; ++p) {
        const int row = p * 32 + lrow;
        v[p] = make_float4(0.f, 0.f, 0.f, 0.f);
        if (row < SLOT_NEED) {
            const int s = tb + row;
            if (interior || s < SLOTS) v[p] = xin[(size_t)s * 128 + rt * 8 + c];
        }
    }
#pragma unroll
    for (int p = 0; p < 5; ++p) {
        const int row = p * 32 + lrow;
        if (row < SLOT_NEED) {
            float* dst = &tile[row * R_PAD + 4 * c];   // banks all distinct
            dst[0] = v[p].x; dst[1] = v[p].y; dst[2] = v[p].z; dst[3] = v[p].w;
        }
    }
    __syncthreads();

    // ---- Store phase: warp ty -> (q = ty>>1, half = ty&1); lane = t pair ----
    // Row rl has shift delta = 2*(rl mod 4); loop j = rl mod 4, m = rl / 4.
    const int q    = ty >> 1;
    const int half = ty & 1;
    const int t0   = tb + half * 64 + 2 * tx;   // even
    const int row0 = half * 64 + 2 * tx + q;    // slot row for t0

    float* __restrict__ outq = out + (size_t)bc * ROWS * T_OUT
                                   + (size_t)(q * 512 + rt * 32) * T_OUT;

#pragma unroll
    for (int j = 0; j < 4; ++j) {               // delta = 2j
        const int t = t0 + 2 * j;
        const float* __restrict__ src = &tile[(row0 + 2 * j) * R_PAD];
        if (interior || t < T_OUT) {            // t even, T_OUT even -> pair valid
            float* o = outq + (size_t)j * T_OUT + t;
#pragma unroll
            for (int m = 0; m < 8; ++m) {
                const int rl = 4 * m + j;       // rows with rl mod 4 == j
                float2 w;
                w.x = src[rl];                  // tile[row][rl]
                w.y = src[R_PAD + rl];          // tile[row+1][rl] -> t+1
                __stcs((float2*)(o + (size_t)(4 * m) * T_OUT), w);  // 32B-aligned run
            }
        }
    }

    // ---- tt==0: prepend uncovered heads t in [0, 2j) for rows rl == j (mod 4) ----
    if (tt == 0 && half == 0 && tx >= 29) {
        const int p = 31 - tx;                  // pair index 0..2
#pragma unroll
        for (int j = 1; j < 4; ++j) {
            if (p < j) {
                const int t = 2 * p;
                const float* __restrict__ src = &tile[(2 * p + q) * R_PAD];
                float* o = outq + (size_t)j * T_OUT + t;
#pragma unroll
                for (int m = 0; m < 8; ++m) {
                    const int rl = 4 * m + j;
                    float2 w;
                    w.x = src[rl];
                    w.y = src[R_PAD + rl];
                    __stcs((float2*)(o + (size_t)(4 * m) * T_OUT), w);
                }
            }
        }
    }
}

extern "C" void kernel_launch(void* const* d_in, const int* in_sizes, int n_in,
                              void* d_out, int out_size) {
    const float4* x = (const float4*)d_in[0];
    float* out = (float*)d_out;

    dim3 block(32, 8, 1);
    dim3 grid(16, 8, 16);   // (r tiles of 32, t tiles of 128, bc)
    enframe_kernel<<<grid, block>>>(x, out);
}